// round 9
// baseline (speedup 1.0000x reference)
#include <cuda_runtime.h>
#include <cuda_bf16.h>
#include <cstdint>
#include <cstddef>

// Problem constants
#define BATCH   8
#define CDIM    384
#define HH      56
#define WWID    56
#define LTOT    (HH * WWID)      // 3136
#define NHEADS  12
#define HDIM    32
#define K2      9
#define MA      (K2 * K2 * NHEADS)   // 972
#define MCAT    (CDIM + MA)          // 1356

// ---------------------------------------------------------------------------
// Device scratch (no cudaMalloc allowed)
// ---------------------------------------------------------------------------
__device__ float g_v[(size_t)BATCH * CDIM * LTOT];         // v projection fp32
__device__ float g_a[(size_t)BATCH * MA   * LTOT];         // attn logits fp32
__device__ __nv_bfloat16 g_xhi[(size_t)BATCH * CDIM * LTOT];
__device__ __nv_bfloat16 g_xlo[(size_t)BATCH * CDIM * LTOT];
__device__ __nv_bfloat16 g_whi[(size_t)MCAT * CDIM];       // [v_w ; attn_w]
__device__ __nv_bfloat16 g_wlo[(size_t)MCAT * CDIM];
__device__ __nv_bfloat16 g_pwhi[(size_t)CDIM * CDIM];
__device__ __nv_bfloat16 g_pwlo[(size_t)CDIM * CDIM];
__device__ __nv_bfloat16 g_fhi[(size_t)BATCH * CDIM * LTOT];  // fold out hi
__device__ __nv_bfloat16 g_flo[(size_t)BATCH * CDIM * LTOT];  // fold out lo

// ---------------------------------------------------------------------------
// fp32 -> (bf16 hi, bf16 lo) split. lo = x - float(hi). Vectorized x4.
// ---------------------------------------------------------------------------
__global__ __launch_bounds__(256) void split_f32(
    const float4* __restrict__ in, uint2* __restrict__ hi, uint2* __restrict__ lo, int n4)
{
    int i = blockIdx.x * blockDim.x + threadIdx.x;
    if (i >= n4) return;
    float4 v = in[i];
    __nv_bfloat16 h0 = __float2bfloat16(v.x), h1 = __float2bfloat16(v.y);
    __nv_bfloat16 h2 = __float2bfloat16(v.z), h3 = __float2bfloat16(v.w);
    __nv_bfloat16 l0 = __float2bfloat16(v.x - __bfloat162float(h0));
    __nv_bfloat16 l1 = __float2bfloat16(v.y - __bfloat162float(h1));
    __nv_bfloat16 l2 = __float2bfloat16(v.z - __bfloat162float(h2));
    __nv_bfloat16 l3 = __float2bfloat16(v.w - __bfloat162float(h3));
    __nv_bfloat162 hp0 = __halves2bfloat162(h0, h1), hp1 = __halves2bfloat162(h2, h3);
    __nv_bfloat162 lp0 = __halves2bfloat162(l0, l1), lp1 = __halves2bfloat162(l2, l3);
    uint2 ho, loo;
    ho.x  = *(uint32_t*)&hp0;  ho.y  = *(uint32_t*)&hp1;
    loo.x = *(uint32_t*)&lp0;  loo.y = *(uint32_t*)&lp1;
    hi[i] = ho;
    lo[i] = loo;
}

// ---------------------------------------------------------------------------
// Tensor-core GEMM (legacy mma.sync path — tcgen05 unavailable: harness
// compiles PTX at compute_103 which rejects tcgen05).
// C[b][m][n] = sum_k A[m][k] * B[b][k][n], precision-split bf16 3 terms.
// Block 128(M) x 128(N), k-step 16, 8 warps (2x4), warp tile 64x32.
// 4-stage cp.async ring, ONE __syncthreads per k-step.
// ---------------------------------------------------------------------------
#define KSTEPS 24
#define NSTAGE 4
// per-stage layout (bf16 element offsets); A padded stride 24, B padded 136
#define SA_H 0
#define SA_L 3072                 // 128*24
#define SB_H 6144
#define SB_L 8320                 // + 16*136
#define STAGE_ELEMS 10496
#define STAGE_BYTES (STAGE_ELEMS * 2)        // 20992
#define GEMM_SMEM   (NSTAGE * STAGE_BYTES)   // 83968

__device__ __forceinline__ void cp_async16(uint32_t dst, const void* src, int srcsize) {
    asm volatile("cp.async.cg.shared.global [%0], [%1], 16, %2;\n"
                 :: "r"(dst), "l"(src), "r"(srcsize));
}
__device__ __forceinline__ void ldsm4(uint32_t* r, uint32_t addr) {
    asm volatile("ldmatrix.sync.aligned.m8n8.x4.shared.b16 {%0,%1,%2,%3}, [%4];\n"
                 : "=r"(r[0]), "=r"(r[1]), "=r"(r[2]), "=r"(r[3]) : "r"(addr));
}
__device__ __forceinline__ void ldsm4t(uint32_t* r, uint32_t addr) {
    asm volatile("ldmatrix.sync.aligned.m8n8.x4.trans.shared.b16 {%0,%1,%2,%3}, [%4];\n"
                 : "=r"(r[0]), "=r"(r[1]), "=r"(r[2]), "=r"(r[3]) : "r"(addr));
}
__device__ __forceinline__ void mma16816(float* d, const uint32_t* a, const uint32_t* b) {
    asm volatile(
        "mma.sync.aligned.m16n8k16.row.col.f32.bf16.bf16.f32 "
        "{%0,%1,%2,%3}, {%4,%5,%6,%7}, {%8,%9}, {%0,%1,%2,%3};\n"
        : "+f"(d[0]), "+f"(d[1]), "+f"(d[2]), "+f"(d[3])
        : "r"(a[0]), "r"(a[1]), "r"(a[2]), "r"(a[3]), "r"(b[0]), "r"(b[1]));
}

__global__ __launch_bounds__(256) void hgemm128(
    const __nv_bfloat16* __restrict__ Ahi, const __nv_bfloat16* __restrict__ Alo,
    const __nv_bfloat16* __restrict__ Bhi, const __nv_bfloat16* __restrict__ Blo,
    const float* __restrict__ bias,
    float* __restrict__ C0, long sC0,
    float* __restrict__ C1, long sC1,
    int M, int Msplit)
{
    extern __shared__ __align__(16) __nv_bfloat16 smbuf[];

    const int b   = blockIdx.z;
    const int bm  = blockIdx.y * 128;
    const int bn  = blockIdx.x * 128;
    const int tid = threadIdx.x;
    const int wid = tid >> 5, lane = tid & 31;
    const int wm  = wid >> 2, wn = wid & 3;

    uint32_t smem_u32 = (uint32_t)__cvta_generic_to_shared(smbuf);

    const long sB = (long)CDIM * LTOT;
    const __nv_bfloat16* Bhib = Bhi + (long)b * sB;
    const __nv_bfloat16* Blob = Blo + (long)b * sB;

    // A cp.async assignment: one 16B chunk per thread per (hi/lo)
    const int a_row = tid >> 1;
    const int a_kh  = (tid & 1) * 8;
    const bool a_ok = (bm + a_row) < M;
    const int a_sz  = a_ok ? 16 : 0;
    const __nv_bfloat16* a_src_hi = Ahi + (long)(bm + (a_ok ? a_row : 0)) * CDIM + a_kh;
    const __nv_bfloat16* a_src_lo = Alo + (long)(bm + (a_ok ? a_row : 0)) * CDIM + a_kh;
    const uint32_t a_dst = (uint32_t)(a_row * 24 + a_kh);

    // B cp.async assignment
    const int b_row = tid >> 4;          // 0..15 (k within step)
    const int b_col = (tid & 15) * 8;    // 0..120
    const bool b_ok = (bn + b_col + 8) <= LTOT;
    const int b_sz  = b_ok ? 16 : 0;
    const long b_off = bn + (b_ok ? b_col : 0);
    const uint32_t b_dst = (uint32_t)(b_row * 136 + b_col);

#define ISSUE(ks) do {                                                             \
        int _k0 = (ks) * 16;                                                       \
        uint32_t _base = smem_u32 + (uint32_t)((ks) & (NSTAGE - 1)) * STAGE_BYTES; \
        cp_async16(_base + (SA_H + a_dst) * 2, a_src_hi + _k0, a_sz);              \
        cp_async16(_base + (SA_L + a_dst) * 2, a_src_lo + _k0, a_sz);              \
        cp_async16(_base + (SB_H + b_dst) * 2,                                     \
                   Bhib + (long)(_k0 + b_row) * LTOT + b_off, b_sz);               \
        cp_async16(_base + (SB_L + b_dst) * 2,                                     \
                   Blob + (long)(_k0 + b_row) * LTOT + b_off, b_sz);               \
        asm volatile("cp.async.commit_group;\n" ::: "memory");                     \
    } while (0)

    float d[4][4][4];
#pragma unroll
    for (int mt = 0; mt < 4; mt++)
#pragma unroll
        for (int nt = 0; nt < 4; nt++)
#pragma unroll
            for (int q = 0; q < 4; q++) d[mt][nt][q] = 0.f;

    // ldmatrix lane addressing
    const int lrow = (lane < 16) ? lane : (lane - 16);
    const int lcol = (lane < 16) ? 0 : 8;

    ISSUE(0);
    ISSUE(1);
    ISSUE(2);

    for (int ks = 0; ks < KSTEPS; ks++) {
        // stage ks complete when <= 2 newer groups outstanding
        if (ks <= KSTEPS - 3)
            asm volatile("cp.async.wait_group 2;\n" ::: "memory");
        else if (ks == KSTEPS - 2)
            asm volatile("cp.async.wait_group 1;\n" ::: "memory");
        else
            asm volatile("cp.async.wait_group 0;\n" ::: "memory");
        __syncthreads();

        // Refill the ring: buffer (ks+3)&3 == (ks-1)&3, finished last iter,
        // protected by the barrier above. No second barrier needed.
        if (ks + 3 < KSTEPS) ISSUE(ks + 3);

        uint32_t sbase = smem_u32 + (uint32_t)(ks & (NSTAGE - 1)) * STAGE_BYTES;

        uint32_t ah[4][4], al[4][4], bh[4][2], bl[4][2];
#pragma unroll
        for (int mt = 0; mt < 4; mt++) {
            uint32_t off = (uint32_t)((wm * 64 + mt * 16 + lrow) * 24 + lcol) * 2;
            ldsm4(ah[mt], sbase + SA_H * 2 + off);
            ldsm4(al[mt], sbase + SA_L * 2 + off);
        }
#pragma unroll
        for (int np = 0; np < 2; np++) {
            uint32_t off = (uint32_t)(lrow * 136 + wn * 32 + np * 16 + lcol) * 2;
            uint32_t t[4];
            ldsm4t(t, sbase + SB_H * 2 + off);
            bh[2 * np][0] = t[0]; bh[2 * np][1] = t[1];
            bh[2 * np + 1][0] = t[2]; bh[2 * np + 1][1] = t[3];
            ldsm4t(t, sbase + SB_L * 2 + off);
            bl[2 * np][0] = t[0]; bl[2 * np][1] = t[1];
            bl[2 * np + 1][0] = t[2]; bl[2 * np + 1][1] = t[3];
        }
#pragma unroll
        for (int mt = 0; mt < 4; mt++)
#pragma unroll
            for (int nt = 0; nt < 4; nt++) {
                mma16816(d[mt][nt], ah[mt], bh[nt]);
                mma16816(d[mt][nt], al[mt], bh[nt]);
                mma16816(d[mt][nt], ah[mt], bl[nt]);
            }
    }
#undef ISSUE

    // epilogue
    const int grp = lane >> 2, tig = lane & 3;
#pragma unroll
    for (int mt = 0; mt < 4; mt++) {
#pragma unroll
        for (int nt = 0; nt < 4; nt++) {
            int col = bn + wn * 32 + nt * 8 + tig * 2;
            if (col >= LTOT) continue;
#pragma unroll
            for (int half = 0; half < 2; half++) {
                int r = bm + wm * 64 + mt * 16 + grp + half * 8;
                if (r >= M) continue;
                float v0 = d[mt][nt][half * 2 + 0];
                float v1 = d[mt][nt][half * 2 + 1];
                if (r < Msplit) {
                    float bs = bias ? bias[r] : 0.f;
                    float2 o; o.x = v0 + bs; o.y = v1 + bs;
                    *(float2*)(C0 + (long)b * sC0 + (long)r * LTOT + col) = o;
                } else {
                    float2 o; o.x = v0; o.y = v1;
                    *(float2*)(C1 + (long)b * sC1 + (long)(r - Msplit) * LTOT + col) = o;
                }
            }
        }
    }
}

// ---------------------------------------------------------------------------
// Fused softmax + attention + fold (gather form). Writes bf16 hi/lo fold
// in [b][c][l] layout (the GEMM B layout).
// ---------------------------------------------------------------------------
__global__ __launch_bounds__(256) void attn_fold_kernel()
{
    extern __shared__ float smf[];
    float* wgt = smf;                       // [3*56][81]
    float* vsm = smf + 3 * 56 * 81;         // [32][5][60]

    const int h = blockIdx.x;
    const int n = blockIdx.y;
    const int b = blockIdx.z;
    const int tid = threadIdx.x;

    const float* abase = g_a + (size_t)b * MA * LTOT + (size_t)n * LTOT;
    for (int i = 0; i < 9; i++) {
        for (int t = tid; t < 3 * 56; t += 256) {
            int srow = t / 56;
            int wp   = t - srow * 56;
            int hp   = h - 1 + srow;
            if (hp < 0 || hp >= HH) continue;
            const float* ap = abase + (size_t)(i * 9) * 12 * LTOT + (size_t)hp * WWID + wp;
            float lg[9];
            float mx = -1e30f;
#pragma unroll
            for (int dd = 0; dd < 9; dd++) {
                lg[dd] = ap[(size_t)dd * 12 * LTOT];
                mx = fmaxf(mx, lg[dd]);
            }
            float s = 0.f;
#pragma unroll
            for (int dd = 0; dd < 9; dd++) { lg[dd] = __expf(lg[dd] - mx); s += lg[dd]; }
            float inv = 1.f / s;
            float* wout = wgt + t * 81 + i * 9;
#pragma unroll
            for (int dd = 0; dd < 9; dd++) wout[dd] = lg[dd] * inv;
        }
    }

    const float* vbase = g_v + ((size_t)b * CDIM + (size_t)n * HDIM) * LTOT;
    for (int idx = tid; idx < 32 * 5 * 60; idx += 256) {
        int c   = idx / 300;
        int rem = idx - c * 300;
        int r   = rem / 60;
        int col = rem - r * 60;
        int gr = h - 2 + r;
        int gc = col - 2;
        float val = 0.f;
        if (gr >= 0 && gr < HH && gc >= 0 && gc < WWID)
            val = vbase[(size_t)c * LTOT + gr * WWID + gc];
        vsm[idx] = val;
    }
    __syncthreads();

    if (tid < 224) {
        int w  = tid % 56;
        int cq = tid / 56;

        float wsum[25];
#pragma unroll
        for (int q = 0; q < 25; q++) wsum[q] = 0.f;

#pragma unroll
        for (int ii = 0; ii < 3; ii++) {
            int hp = h + 1 - ii;
            if (hp < 0 || hp >= HH) continue;
#pragma unroll
            for (int jj = 0; jj < 3; jj++) {
                int wp = w + 1 - jj;
                if (wp < 0 || wp >= WWID) continue;
                const float* wrow = wgt + ((2 - ii) * 56 + wp) * 81 + (ii * 3 + jj) * 9;
#pragma unroll
                for (int di = 0; di < 3; di++)
#pragma unroll
                    for (int dj = 0; dj < 3; dj++)
                        wsum[(di - ii + 2) * 5 + (dj - jj + 2)] += wrow[di * 3 + dj];
            }
        }

        float acc[8];
#pragma unroll
        for (int j = 0; j < 8; j++) acc[j] = 0.f;

#pragma unroll
        for (int dr = 0; dr < 5; dr++)
#pragma unroll
            for (int dc = 0; dc < 5; dc++) {
                float wv = wsum[dr * 5 + dc];
                int off = dr * 60 + (w + dc);
#pragma unroll
                for (int j = 0; j < 8; j++)
                    acc[j] += wv * vsm[(cq * 8 + j) * 300 + off];
            }

        size_t obase = ((size_t)b * CDIM + (size_t)n * HDIM + cq * 8) * LTOT
                     + (size_t)h * WWID + w;
#pragma unroll
        for (int j = 0; j < 8; j++) {
            float a = acc[j];
            __nv_bfloat16 hh = __float2bfloat16(a);
            __nv_bfloat16 ll = __float2bfloat16(a - __bfloat162float(hh));
            g_fhi[obase + (size_t)j * LTOT] = hh;
            g_flo[obase + (size_t)j * LTOT] = ll;
        }
    }
}

// ---------------------------------------------------------------------------
// Launch
// ---------------------------------------------------------------------------
extern "C" void kernel_launch(void* const* d_in, const int* in_sizes, int n_in,
                              void* d_out, int out_size)
{
    const float* x      = (const float*)d_in[0];
    const float* v_w    = (const float*)d_in[1];
    const float* v_b    = (const float*)d_in[2];
    const float* attn_w = (const float*)d_in[3];
    const float* proj_w = (const float*)d_in[4];
    float* out = (float*)d_out;

    float *gv, *ga;
    __nv_bfloat16 *gxh, *gxl, *gwh, *gwl, *gph, *gpl, *gfh, *gfl;
    cudaGetSymbolAddress((void**)&gv,  g_v);
    cudaGetSymbolAddress((void**)&ga,  g_a);
    cudaGetSymbolAddress((void**)&gxh, g_xhi);
    cudaGetSymbolAddress((void**)&gxl, g_xlo);
    cudaGetSymbolAddress((void**)&gwh, g_whi);
    cudaGetSymbolAddress((void**)&gwl, g_wlo);
    cudaGetSymbolAddress((void**)&gph, g_pwhi);
    cudaGetSymbolAddress((void**)&gpl, g_pwlo);
    cudaGetSymbolAddress((void**)&gfh, g_fhi);
    cudaGetSymbolAddress((void**)&gfl, g_flo);

    cudaFuncSetAttribute(hgemm128, cudaFuncAttributeMaxDynamicSharedMemorySize, GEMM_SMEM);

    // 0. precision splits
    {
        int n4 = (BATCH * CDIM * LTOT) / 4;
        split_f32<<<(n4 + 255) / 256, 256>>>((const float4*)x, (uint2*)gxh, (uint2*)gxl, n4);
        int nw = (CDIM * CDIM) / 4;
        split_f32<<<(nw + 255) / 256, 256>>>((const float4*)v_w, (uint2*)gwh, (uint2*)gwl, nw);
        int na = (MA * CDIM) / 4;
        split_f32<<<(na + 255) / 256, 256>>>((const float4*)attn_w,
                                             (uint2*)(gwh + (size_t)CDIM * CDIM),
                                             (uint2*)(gwl + (size_t)CDIM * CDIM), na);
        split_f32<<<(nw + 255) / 256, 256>>>((const float4*)proj_w, (uint2*)gph, (uint2*)gpl, nw);
    }

    // 1+2. fused [v_w ; attn_w] @ x  ->  g_v (+bias) and g_a
    {
        dim3 grid((LTOT + 127) / 128, (MCAT + 127) / 128, BATCH);   // 25 x 11 x 8
        hgemm128<<<grid, 256, GEMM_SMEM>>>(gwh, gwl, gxh, gxl, v_b,
                                           gv, (long)CDIM * LTOT,
                                           ga, (long)MA * LTOT,
                                           MCAT, CDIM);
    }

    // 3. fused softmax + attention + fold  (writes bf16 hi/lo fold)
    {
        int smem_bytes = (3 * 56 * 81 + 32 * 5 * 60) * (int)sizeof(float); // 92832
        cudaFuncSetAttribute(attn_fold_kernel,
                             cudaFuncAttributeMaxDynamicSharedMemorySize, smem_bytes);
        dim3 grid(HH, NHEADS, BATCH);
        attn_fold_kernel<<<grid, 256, smem_bytes>>>();
    }

    // 4. out = proj_w @ fold
    {
        dim3 grid((LTOT + 127) / 128, (CDIM + 127) / 128, BATCH);   // 25 x 3 x 8
        hgemm128<<<grid, 256, GEMM_SMEM>>>(gph, gpl, gfh, gfl, nullptr,
                                           out, (long)CDIM * LTOT,
                                           out, (long)CDIM * LTOT,
                                           CDIM, CDIM);
    }
}

// round 11
// speedup vs baseline: 1.0724x; 1.0724x over previous
#include <cuda_runtime.h>
#include <cuda_bf16.h>
#include <cstdint>
#include <cstddef>

// Problem constants
#define BATCH   8
#define CDIM    384
#define HH      56
#define WWID    56
#define LTOT    (HH * WWID)      // 3136
#define NHEADS  12
#define HDIM    32
#define K2      9
#define MA      (K2 * K2 * NHEADS)   // 972
#define MCAT    (CDIM + MA)          // 1356

// ---------------------------------------------------------------------------
// Device scratch (no cudaMalloc allowed)
// ---------------------------------------------------------------------------
__device__ float g_v[(size_t)BATCH * CDIM * LTOT];         // v projection fp32
__device__ float g_a[(size_t)BATCH * MA   * LTOT];         // attn logits -> softmaxed in place
__device__ __nv_bfloat16 g_xhi[(size_t)BATCH * CDIM * LTOT];
__device__ __nv_bfloat16 g_xlo[(size_t)BATCH * CDIM * LTOT];
__device__ __nv_bfloat16 g_whi[(size_t)MCAT * CDIM];       // [v_w ; attn_w]
__device__ __nv_bfloat16 g_wlo[(size_t)MCAT * CDIM];
__device__ __nv_bfloat16 g_pwhi[(size_t)CDIM * CDIM];
__device__ __nv_bfloat16 g_pwlo[(size_t)CDIM * CDIM];
__device__ __nv_bfloat16 g_fhi[(size_t)BATCH * CDIM * LTOT];  // fold out hi
__device__ __nv_bfloat16 g_flo[(size_t)BATCH * CDIM * LTOT];  // fold out lo

// ---------------------------------------------------------------------------
// fp32 -> (bf16 hi, bf16 lo) split
// ---------------------------------------------------------------------------
__global__ __launch_bounds__(256) void split_f32(
    const float4* __restrict__ in, uint2* __restrict__ hi, uint2* __restrict__ lo, int n4)
{
    int i = blockIdx.x * blockDim.x + threadIdx.x;
    if (i >= n4) return;
    float4 v = in[i];
    __nv_bfloat16 h0 = __float2bfloat16(v.x), h1 = __float2bfloat16(v.y);
    __nv_bfloat16 h2 = __float2bfloat16(v.z), h3 = __float2bfloat16(v.w);
    __nv_bfloat16 l0 = __float2bfloat16(v.x - __bfloat162float(h0));
    __nv_bfloat16 l1 = __float2bfloat16(v.y - __bfloat162float(h1));
    __nv_bfloat16 l2 = __float2bfloat16(v.z - __bfloat162float(h2));
    __nv_bfloat16 l3 = __float2bfloat16(v.w - __bfloat162float(h3));
    __nv_bfloat162 hp0 = __halves2bfloat162(h0, h1), hp1 = __halves2bfloat162(h2, h3);
    __nv_bfloat162 lp0 = __halves2bfloat162(l0, l1), lp1 = __halves2bfloat162(l2, l3);
    uint2 ho, loo;
    ho.x  = *(uint32_t*)&hp0;  ho.y  = *(uint32_t*)&hp1;
    loo.x = *(uint32_t*)&lp0;  loo.y = *(uint32_t*)&lp1;
    hi[i] = ho;
    lo[i] = loo;
}

// ---------------------------------------------------------------------------
// Tensor-core GEMM (legacy mma.sync — tcgen05 rejected at compute_103).
// EXACT Round-5 structure (proven fastest): 2 stages, wait->sync->compute->
// sync->issue. Do not restructure (4-stage single-barrier variant regressed).
// ---------------------------------------------------------------------------
#define KSTEPS 24
#define SA_H 0
#define SA_L 3072                 // 128*24
#define SB_H 6144
#define SB_L 8320                 // + 16*136
#define STAGE_ELEMS 10496
#define STAGE_BYTES (STAGE_ELEMS * 2)

__device__ __forceinline__ void cp_async16(uint32_t dst, const void* src, int srcsize) {
    asm volatile("cp.async.cg.shared.global [%0], [%1], 16, %2;\n"
                 :: "r"(dst), "l"(src), "r"(srcsize));
}
__device__ __forceinline__ void ldsm4(uint32_t* r, uint32_t addr) {
    asm volatile("ldmatrix.sync.aligned.m8n8.x4.shared.b16 {%0,%1,%2,%3}, [%4];\n"
                 : "=r"(r[0]), "=r"(r[1]), "=r"(r[2]), "=r"(r[3]) : "r"(addr));
}
__device__ __forceinline__ void ldsm4t(uint32_t* r, uint32_t addr) {
    asm volatile("ldmatrix.sync.aligned.m8n8.x4.trans.shared.b16 {%0,%1,%2,%3}, [%4];\n"
                 : "=r"(r[0]), "=r"(r[1]), "=r"(r[2]), "=r"(r[3]) : "r"(addr));
}
__device__ __forceinline__ void mma16816(float* d, const uint32_t* a, const uint32_t* b) {
    asm volatile(
        "mma.sync.aligned.m16n8k16.row.col.f32.bf16.bf16.f32 "
        "{%0,%1,%2,%3}, {%4,%5,%6,%7}, {%8,%9}, {%0,%1,%2,%3};\n"
        : "+f"(d[0]), "+f"(d[1]), "+f"(d[2]), "+f"(d[3])
        : "r"(a[0]), "r"(a[1]), "r"(a[2]), "r"(a[3]), "r"(b[0]), "r"(b[1]));
}

__global__ __launch_bounds__(256) void hgemm128(
    const __nv_bfloat16* __restrict__ Ahi, const __nv_bfloat16* __restrict__ Alo,
    const __nv_bfloat16* __restrict__ Bhi, const __nv_bfloat16* __restrict__ Blo,
    const float* __restrict__ bias,
    float* __restrict__ C0, long sC0,
    float* __restrict__ C1, long sC1,
    int M, int Msplit)
{
    __shared__ __align__(16) __nv_bfloat16 sm[2][STAGE_ELEMS];

    const int b   = blockIdx.z;
    const int bm  = blockIdx.y * 128;
    const int bn  = blockIdx.x * 128;
    const int tid = threadIdx.x;
    const int wid = tid >> 5, lane = tid & 31;
    const int wm  = wid >> 2, wn = wid & 3;

    uint32_t smem_u32 = (uint32_t)__cvta_generic_to_shared(&sm[0][0]);

    const long sB = (long)CDIM * LTOT;
    const __nv_bfloat16* Bhib = Bhi + (long)b * sB;
    const __nv_bfloat16* Blob = Blo + (long)b * sB;

    const int a_row = tid >> 1;
    const int a_kh  = (tid & 1) * 8;
    const bool a_ok = (bm + a_row) < M;
    const int a_sz  = a_ok ? 16 : 0;
    const __nv_bfloat16* a_src_hi = Ahi + (long)(bm + (a_ok ? a_row : 0)) * CDIM + a_kh;
    const __nv_bfloat16* a_src_lo = Alo + (long)(bm + (a_ok ? a_row : 0)) * CDIM + a_kh;
    const uint32_t a_dst = (uint32_t)(a_row * 24 + a_kh);

    const int b_row = tid >> 4;
    const int b_col = (tid & 15) * 8;
    const bool b_ok = (bn + b_col + 8) <= LTOT;
    const int b_sz  = b_ok ? 16 : 0;
    const long b_off = bn + (b_ok ? b_col : 0);
    const uint32_t b_dst = (uint32_t)(b_row * 136 + b_col);

#define ISSUE(ks, buf) do {                                                        \
        int _k0 = (ks) * 16;                                                       \
        uint32_t _base = smem_u32 + (uint32_t)(buf) * STAGE_BYTES;                 \
        cp_async16(_base + (SA_H + a_dst) * 2, a_src_hi + _k0, a_sz);              \
        cp_async16(_base + (SA_L + a_dst) * 2, a_src_lo + _k0, a_sz);              \
        cp_async16(_base + (SB_H + b_dst) * 2,                                     \
                   Bhib + (long)(_k0 + b_row) * LTOT + b_off, b_sz);               \
        cp_async16(_base + (SB_L + b_dst) * 2,                                     \
                   Blob + (long)(_k0 + b_row) * LTOT + b_off, b_sz);               \
        asm volatile("cp.async.commit_group;\n" ::: "memory");                     \
    } while (0)

    float d[4][4][4];
#pragma unroll
    for (int i = 0; i < 8; i++)
#pragma unroll
        for (int j = 0; j < 8; j++) d[i >> 1][j >> 1][(i & 1) * 2 + (j & 1)] = 0.f;

    const int lrow = (lane < 16) ? lane : (lane - 16);
    const int lcol = (lane < 16) ? 0 : 8;

    ISSUE(0, 0);
    ISSUE(1, 1);

    for (int ks = 0; ks < KSTEPS; ks++) {
        if (ks == KSTEPS - 1)
            asm volatile("cp.async.wait_group 0;\n" ::: "memory");
        else
            asm volatile("cp.async.wait_group 1;\n" ::: "memory");
        __syncthreads();

        const int buf = ks & 1;
        uint32_t sbase = smem_u32 + (uint32_t)buf * STAGE_BYTES;

        uint32_t ah[4][4], al[4][4], bh[4][2], bl[4][2];
#pragma unroll
        for (int mt = 0; mt < 4; mt++) {
            uint32_t off = (uint32_t)((wm * 64 + mt * 16 + lrow) * 24 + lcol) * 2;
            ldsm4(ah[mt], sbase + SA_H * 2 + off);
            ldsm4(al[mt], sbase + SA_L * 2 + off);
        }
#pragma unroll
        for (int np = 0; np < 2; np++) {
            uint32_t off = (uint32_t)(lrow * 136 + wn * 32 + np * 16 + lcol) * 2;
            uint32_t t[4];
            ldsm4t(t, sbase + SB_H * 2 + off);
            bh[2 * np][0] = t[0]; bh[2 * np][1] = t[1];
            bh[2 * np + 1][0] = t[2]; bh[2 * np + 1][1] = t[3];
            ldsm4t(t, sbase + SB_L * 2 + off);
            bl[2 * np][0] = t[0]; bl[2 * np][1] = t[1];
            bl[2 * np + 1][0] = t[2]; bl[2 * np + 1][1] = t[3];
        }
#pragma unroll
        for (int mt = 0; mt < 4; mt++)
#pragma unroll
            for (int nt = 0; nt < 4; nt++) {
                mma16816(d[mt][nt], ah[mt], bh[nt]);
                mma16816(d[mt][nt], al[mt], bh[nt]);
                mma16816(d[mt][nt], ah[mt], bl[nt]);
            }

        __syncthreads();
        if (ks + 2 < KSTEPS) ISSUE(ks + 2, buf);
    }
#undef ISSUE

    const int grp = lane >> 2, tig = lane & 3;
#pragma unroll
    for (int mt = 0; mt < 4; mt++) {
#pragma unroll
        for (int nt = 0; nt < 4; nt++) {
            int col = bn + wn * 32 + nt * 8 + tig * 2;
            if (col >= LTOT) continue;
#pragma unroll
            for (int half = 0; half < 2; half++) {
                int r = bm + wm * 64 + mt * 16 + grp + half * 8;
                if (r >= M) continue;
                float v0 = d[mt][nt][half * 2 + 0];
                float v1 = d[mt][nt][half * 2 + 1];
                if (r < Msplit) {
                    float bs = bias ? bias[r] : 0.f;
                    float2 o; o.x = v0 + bs; o.y = v1 + bs;
                    *(float2*)(C0 + (long)b * sC0 + (long)r * LTOT + col) = o;
                } else {
                    float2 o; o.x = v0; o.y = v1;
                    *(float2*)(C1 + (long)b * sC1 + (long)(r - Msplit) * LTOT + col) = o;
                }
            }
        }
    }
}

// ---------------------------------------------------------------------------
// In-place softmax over d (9 values) for each (b, head, pixel, i).
// Layout preserved: channel o = (i*9+d)*NHEADS + n. Coalesced: consecutive
// threads handle consecutive pixels; each channel slice is contiguous.
// grid (LTOT/224, NHEADS, BATCH), block 224.
// ---------------------------------------------------------------------------
__global__ __launch_bounds__(224) void softmax_kernel()
{
    const int l = blockIdx.x * 224 + threadIdx.x;
    const int n = blockIdx.y;
    const int b = blockIdx.z;
    float* abase = g_a + (size_t)b * MA * LTOT + (size_t)n * LTOT + l;

#pragma unroll
    for (int i = 0; i < 9; i++) {
        float* ap = abase + (size_t)(i * 9) * NHEADS * LTOT;
        float lg[9];
        float mx = -1e30f;
#pragma unroll
        for (int dd = 0; dd < 9; dd++) {
            lg[dd] = ap[(size_t)dd * NHEADS * LTOT];
            mx = fmaxf(mx, lg[dd]);
        }
        float s = 0.f;
#pragma unroll
        for (int dd = 0; dd < 9; dd++) { lg[dd] = __expf(lg[dd] - mx); s += lg[dd]; }
        float inv = 1.f / s;
#pragma unroll
        for (int dd = 0; dd < 9; dd++)
            ap[(size_t)dd * NHEADS * LTOT] = lg[dd] * inv;
    }
}

// ---------------------------------------------------------------------------
// Fused attention + fold (gather). Weights precomputed (softmaxed g_a).
// Phase 1 is now a pure coalesced copy into smem. Writes bf16 hi/lo fold.
// ---------------------------------------------------------------------------
__global__ __launch_bounds__(256) void attn_fold_kernel()
{
    extern __shared__ float smf[];
    float* wgt = smf;                       // [3*56][81]
    float* vsm = smf + 3 * 56 * 81;         // [32][5][60]

    const int h = blockIdx.x;
    const int n = blockIdx.y;
    const int b = blockIdx.z;
    const int tid = threadIdx.x;

    // phase 1: copy precomputed softmax weights, coalesced per channel slice
    const float* abase = g_a + (size_t)b * MA * LTOT + (size_t)n * LTOT;
    {
        const int h0 = h - 1;
        // rows t in [0,168): hp = h0 + t/56, wp = t%56
        for (int dd = 0; dd < 81; dd++) {
            const float* src = abase + (size_t)dd * NHEADS * LTOT + h0 * WWID;
            for (int t = tid; t < 168; t += 256) {
                int hp = h0 + t / 56;
                if (hp >= 0 && hp < HH)
                    wgt[t * 81 + dd] = src[t];
            }
        }
    }

    // phase 2: v tile (zero-padded halo)
    const float* vbase = g_v + ((size_t)b * CDIM + (size_t)n * HDIM) * LTOT;
    for (int idx = tid; idx < 32 * 5 * 60; idx += 256) {
        int c   = idx / 300;
        int rem = idx - c * 300;
        int r   = rem / 60;
        int col = rem - r * 60;
        int gr = h - 2 + r;
        int gc = col - 2;
        float val = 0.f;
        if (gr >= 0 && gr < HH && gc >= 0 && gc < WWID)
            val = vbase[(size_t)c * LTOT + gr * WWID + gc];
        vsm[idx] = val;
    }
    __syncthreads();

    // phase 3
    if (tid < 224) {
        int w  = tid % 56;
        int cq = tid / 56;

        float wsum[25];
#pragma unroll
        for (int q = 0; q < 25; q++) wsum[q] = 0.f;

#pragma unroll
        for (int ii = 0; ii < 3; ii++) {
            int hp = h + 1 - ii;
            if (hp < 0 || hp >= HH) continue;
#pragma unroll
            for (int jj = 0; jj < 3; jj++) {
                int wp = w + 1 - jj;
                if (wp < 0 || wp >= WWID) continue;
                const float* wrow = wgt + ((2 - ii) * 56 + wp) * 81 + (ii * 3 + jj) * 9;
#pragma unroll
                for (int di = 0; di < 3; di++)
#pragma unroll
                    for (int dj = 0; dj < 3; dj++)
                        wsum[(di - ii + 2) * 5 + (dj - jj + 2)] += wrow[di * 3 + dj];
            }
        }

        float acc[8];
#pragma unroll
        for (int j = 0; j < 8; j++) acc[j] = 0.f;

#pragma unroll
        for (int dr = 0; dr < 5; dr++)
#pragma unroll
            for (int dc = 0; dc < 5; dc++) {
                float wv = wsum[dr * 5 + dc];
                int off = dr * 60 + (w + dc);
#pragma unroll
                for (int j = 0; j < 8; j++)
                    acc[j] += wv * vsm[(cq * 8 + j) * 300 + off];
            }

        size_t obase = ((size_t)b * CDIM + (size_t)n * HDIM + cq * 8) * LTOT
                     + (size_t)h * WWID + w;
#pragma unroll
        for (int j = 0; j < 8; j++) {
            float a = acc[j];
            __nv_bfloat16 hh = __float2bfloat16(a);
            __nv_bfloat16 ll = __float2bfloat16(a - __bfloat162float(hh));
            g_fhi[obase + (size_t)j * LTOT] = hh;
            g_flo[obase + (size_t)j * LTOT] = ll;
        }
    }
}

// ---------------------------------------------------------------------------
// Launch. Order chosen so launch #6 (ncu -s 5 -c 1) is attn_fold_kernel.
// ---------------------------------------------------------------------------
extern "C" void kernel_launch(void* const* d_in, const int* in_sizes, int n_in,
                              void* d_out, int out_size)
{
    const float* x      = (const float*)d_in[0];
    const float* v_w    = (const float*)d_in[1];
    const float* v_b    = (const float*)d_in[2];
    const float* attn_w = (const float*)d_in[3];
    const float* proj_w = (const float*)d_in[4];
    float* out = (float*)d_out;

    float *gv, *ga;
    __nv_bfloat16 *gxh, *gxl, *gwh, *gwl, *gph, *gpl, *gfh, *gfl;
    cudaGetSymbolAddress((void**)&gv,  g_v);
    cudaGetSymbolAddress((void**)&ga,  g_a);
    cudaGetSymbolAddress((void**)&gxh, g_xhi);
    cudaGetSymbolAddress((void**)&gxl, g_xlo);
    cudaGetSymbolAddress((void**)&gwh, g_whi);
    cudaGetSymbolAddress((void**)&gwl, g_wlo);
    cudaGetSymbolAddress((void**)&gph, g_pwhi);
    cudaGetSymbolAddress((void**)&gpl, g_pwlo);
    cudaGetSymbolAddress((void**)&gfh, g_fhi);
    cudaGetSymbolAddress((void**)&gfl, g_flo);

    // 1-3. splits for x and [v_w ; attn_w]
    {
        int n4 = (BATCH * CDIM * LTOT) / 4;
        split_f32<<<(n4 + 255) / 256, 256>>>((const float4*)x, (uint2*)gxh, (uint2*)gxl, n4);
        int nw = (CDIM * CDIM) / 4;
        split_f32<<<(nw + 255) / 256, 256>>>((const float4*)v_w, (uint2*)gwh, (uint2*)gwl, nw);
        int na = (MA * CDIM) / 4;
        split_f32<<<(na + 255) / 256, 256>>>((const float4*)attn_w,
                                             (uint2*)(gwh + (size_t)CDIM * CDIM),
                                             (uint2*)(gwl + (size_t)CDIM * CDIM), na);
    }

    // 4. fused [v_w ; attn_w] @ x  ->  g_v (+bias) and g_a
    {
        dim3 grid((LTOT + 127) / 128, (MCAT + 127) / 128, BATCH);   // 25 x 11 x 8
        hgemm128<<<grid, 256>>>(gwh, gwl, gxh, gxl, v_b,
                                gv, (long)CDIM * LTOT,
                                ga, (long)MA * LTOT,
                                MCAT, CDIM);
    }

    // 5. in-place softmax of attn logits
    {
        dim3 grid(LTOT / 224, NHEADS, BATCH);   // 14 x 12 x 8
        softmax_kernel<<<grid, 224>>>();
    }

    // 6. fused attention + fold  (writes bf16 hi/lo fold)  [profiled launch]
    {
        int smem_bytes = (3 * 56 * 81 + 32 * 5 * 60) * (int)sizeof(float); // 92832
        cudaFuncSetAttribute(attn_fold_kernel,
                             cudaFuncAttributeMaxDynamicSharedMemorySize, smem_bytes);
        dim3 grid(HH, NHEADS, BATCH);
        attn_fold_kernel<<<grid, 256, smem_bytes>>>();
    }

    // 7. split proj weights (needed only by final GEMM)
    {
        int nw = (CDIM * CDIM) / 4;
        split_f32<<<(nw + 255) / 256, 256>>>((const float4*)proj_w, (uint2*)gph, (uint2*)gpl, nw);
    }

    // 8. out = proj_w @ fold
    {
        dim3 grid((LTOT + 127) / 128, (CDIM + 127) / 128, BATCH);   // 25 x 3 x 8
        hgemm128<<<grid, 256>>>(gph, gpl, gfh, gfl, nullptr,
                                out, (long)CDIM * LTOT,
                                out, (long)CDIM * LTOT,
                                CDIM, CDIM);
    }
}

// round 16
// speedup vs baseline: 1.7154x; 1.5996x over previous
#include <cuda_runtime.h>
#include <cuda_bf16.h>
#include <cstdint>
#include <cstddef>

// Problem constants
#define BATCH   8
#define CDIM    384
#define HH      56
#define WWID    56
#define LTOT    (HH * WWID)      // 3136
#define NHEADS  12
#define HDIM    32
#define K2      9
#define MA      (K2 * K2 * NHEADS)   // 972
#define MCAT    (CDIM + MA)          // 1356

// ---------------------------------------------------------------------------
// Device scratch (no cudaMalloc allowed)
// ---------------------------------------------------------------------------
__device__ float g_v[(size_t)BATCH * CDIM * LTOT];         // v projection fp32
__device__ float g_a[(size_t)BATCH * MA   * LTOT];         // attn logits -> softmaxed in place
__device__ __nv_bfloat16 g_xhi[(size_t)BATCH * CDIM * LTOT];
__device__ __nv_bfloat16 g_xlo[(size_t)BATCH * CDIM * LTOT];
__device__ __nv_bfloat16 g_whi[(size_t)MCAT * CDIM];       // [v_w ; attn_w]
__device__ __nv_bfloat16 g_wlo[(size_t)MCAT * CDIM];
__device__ __nv_bfloat16 g_pwhi[(size_t)CDIM * CDIM];
__device__ __nv_bfloat16 g_pwlo[(size_t)CDIM * CDIM];
__device__ __nv_bfloat16 g_fhi[(size_t)BATCH * CDIM * LTOT];  // fold out hi
__device__ __nv_bfloat16 g_flo[(size_t)BATCH * CDIM * LTOT];  // fold out lo

// ---------------------------------------------------------------------------
// fp32 -> (bf16 hi, bf16 lo) split
// ---------------------------------------------------------------------------
__global__ __launch_bounds__(256) void split_f32(
    const float4* __restrict__ in, uint2* __restrict__ hi, uint2* __restrict__ lo, int n4)
{
    int i = blockIdx.x * blockDim.x + threadIdx.x;
    if (i >= n4) return;
    float4 v = in[i];
    __nv_bfloat16 h0 = __float2bfloat16(v.x), h1 = __float2bfloat16(v.y);
    __nv_bfloat16 h2 = __float2bfloat16(v.z), h3 = __float2bfloat16(v.w);
    __nv_bfloat16 l0 = __float2bfloat16(v.x - __bfloat162float(h0));
    __nv_bfloat16 l1 = __float2bfloat16(v.y - __bfloat162float(h1));
    __nv_bfloat16 l2 = __float2bfloat16(v.z - __bfloat162float(h2));
    __nv_bfloat16 l3 = __float2bfloat16(v.w - __bfloat162float(h3));
    __nv_bfloat162 hp0 = __halves2bfloat162(h0, h1), hp1 = __halves2bfloat162(h2, h3);
    __nv_bfloat162 lp0 = __halves2bfloat162(l0, l1), lp1 = __halves2bfloat162(l2, l3);
    uint2 ho, loo;
    ho.x  = *(uint32_t*)&hp0;  ho.y  = *(uint32_t*)&hp1;
    loo.x = *(uint32_t*)&lp0;  loo.y = *(uint32_t*)&lp1;
    hi[i] = ho;
    lo[i] = loo;
}

// ---------------------------------------------------------------------------
// Tensor-core GEMM (legacy mma.sync — tcgen05 rejected at compute_103).
// EXACT Round-5 structure (proven fastest): 2 stages, wait->sync->compute->
// sync->issue. Do not restructure (4-stage single-barrier variant regressed).
// ---------------------------------------------------------------------------
#define KSTEPS 24
#define SA_H 0
#define SA_L 3072                 // 128*24
#define SB_H 6144
#define SB_L 8320                 // + 16*136
#define STAGE_ELEMS 10496
#define STAGE_BYTES (STAGE_ELEMS * 2)

__device__ __forceinline__ void cp_async16(uint32_t dst, const void* src, int srcsize) {
    asm volatile("cp.async.cg.shared.global [%0], [%1], 16, %2;\n"
                 :: "r"(dst), "l"(src), "r"(srcsize));
}
__device__ __forceinline__ void ldsm4(uint32_t* r, uint32_t addr) {
    asm volatile("ldmatrix.sync.aligned.m8n8.x4.shared.b16 {%0,%1,%2,%3}, [%4];\n"
                 : "=r"(r[0]), "=r"(r[1]), "=r"(r[2]), "=r"(r[3]) : "r"(addr));
}
__device__ __forceinline__ void ldsm4t(uint32_t* r, uint32_t addr) {
    asm volatile("ldmatrix.sync.aligned.m8n8.x4.trans.shared.b16 {%0,%1,%2,%3}, [%4];\n"
                 : "=r"(r[0]), "=r"(r[1]), "=r"(r[2]), "=r"(r[3]) : "r"(addr));
}
__device__ __forceinline__ void mma16816(float* d, const uint32_t* a, const uint32_t* b) {
    asm volatile(
        "mma.sync.aligned.m16n8k16.row.col.f32.bf16.bf16.f32 "
        "{%0,%1,%2,%3}, {%4,%5,%6,%7}, {%8,%9}, {%0,%1,%2,%3};\n"
        : "+f"(d[0]), "+f"(d[1]), "+f"(d[2]), "+f"(d[3])
        : "r"(a[0]), "r"(a[1]), "r"(a[2]), "r"(a[3]), "r"(b[0]), "r"(b[1]));
}

__global__ __launch_bounds__(256) void hgemm128(
    const __nv_bfloat16* __restrict__ Ahi, const __nv_bfloat16* __restrict__ Alo,
    const __nv_bfloat16* __restrict__ Bhi, const __nv_bfloat16* __restrict__ Blo,
    const float* __restrict__ bias,
    float* __restrict__ C0, long sC0,
    float* __restrict__ C1, long sC1,
    int M, int Msplit)
{
    __shared__ __align__(16) __nv_bfloat16 sm[2][STAGE_ELEMS];

    const int b   = blockIdx.z;
    const int bm  = blockIdx.y * 128;
    const int bn  = blockIdx.x * 128;
    const int tid = threadIdx.x;
    const int wid = tid >> 5, lane = tid & 31;
    const int wm  = wid >> 2, wn = wid & 3;

    uint32_t smem_u32 = (uint32_t)__cvta_generic_to_shared(&sm[0][0]);

    const long sB = (long)CDIM * LTOT;
    const __nv_bfloat16* Bhib = Bhi + (long)b * sB;
    const __nv_bfloat16* Blob = Blo + (long)b * sB;

    const int a_row = tid >> 1;
    const int a_kh  = (tid & 1) * 8;
    const bool a_ok = (bm + a_row) < M;
    const int a_sz  = a_ok ? 16 : 0;
    const __nv_bfloat16* a_src_hi = Ahi + (long)(bm + (a_ok ? a_row : 0)) * CDIM + a_kh;
    const __nv_bfloat16* a_src_lo = Alo + (long)(bm + (a_ok ? a_row : 0)) * CDIM + a_kh;
    const uint32_t a_dst = (uint32_t)(a_row * 24 + a_kh);

    const int b_row = tid >> 4;
    const int b_col = (tid & 15) * 8;
    const bool b_ok = (bn + b_col + 8) <= LTOT;
    const int b_sz  = b_ok ? 16 : 0;
    const long b_off = bn + (b_ok ? b_col : 0);
    const uint32_t b_dst = (uint32_t)(b_row * 136 + b_col);

#define ISSUE(ks, buf) do {                                                        \
        int _k0 = (ks) * 16;                                                       \
        uint32_t _base = smem_u32 + (uint32_t)(buf) * STAGE_BYTES;                 \
        cp_async16(_base + (SA_H + a_dst) * 2, a_src_hi + _k0, a_sz);              \
        cp_async16(_base + (SA_L + a_dst) * 2, a_src_lo + _k0, a_sz);              \
        cp_async16(_base + (SB_H + b_dst) * 2,                                     \
                   Bhib + (long)(_k0 + b_row) * LTOT + b_off, b_sz);               \
        cp_async16(_base + (SB_L + b_dst) * 2,                                     \
                   Blob + (long)(_k0 + b_row) * LTOT + b_off, b_sz);               \
        asm volatile("cp.async.commit_group;\n" ::: "memory");                     \
    } while (0)

    float d[4][4][4];
#pragma unroll
    for (int i = 0; i < 8; i++)
#pragma unroll
        for (int j = 0; j < 8; j++) d[i >> 1][j >> 1][(i & 1) * 2 + (j & 1)] = 0.f;

    const int lrow = (lane < 16) ? lane : (lane - 16);
    const int lcol = (lane < 16) ? 0 : 8;

    ISSUE(0, 0);
    ISSUE(1, 1);

    for (int ks = 0; ks < KSTEPS; ks++) {
        if (ks == KSTEPS - 1)
            asm volatile("cp.async.wait_group 0;\n" ::: "memory");
        else
            asm volatile("cp.async.wait_group 1;\n" ::: "memory");
        __syncthreads();

        const int buf = ks & 1;
        uint32_t sbase = smem_u32 + (uint32_t)buf * STAGE_BYTES;

        uint32_t ah[4][4], al[4][4], bh[4][2], bl[4][2];
#pragma unroll
        for (int mt = 0; mt < 4; mt++) {
            uint32_t off = (uint32_t)((wm * 64 + mt * 16 + lrow) * 24 + lcol) * 2;
            ldsm4(ah[mt], sbase + SA_H * 2 + off);
            ldsm4(al[mt], sbase + SA_L * 2 + off);
        }
#pragma unroll
        for (int np = 0; np < 2; np++) {
            uint32_t off = (uint32_t)(lrow * 136 + wn * 32 + np * 16 + lcol) * 2;
            uint32_t t[4];
            ldsm4t(t, sbase + SB_H * 2 + off);
            bh[2 * np][0] = t[0]; bh[2 * np][1] = t[1];
            bh[2 * np + 1][0] = t[2]; bh[2 * np + 1][1] = t[3];
            ldsm4t(t, sbase + SB_L * 2 + off);
            bl[2 * np][0] = t[0]; bl[2 * np][1] = t[1];
            bl[2 * np + 1][0] = t[2]; bl[2 * np + 1][1] = t[3];
        }
#pragma unroll
        for (int mt = 0; mt < 4; mt++)
#pragma unroll
            for (int nt = 0; nt < 4; nt++) {
                mma16816(d[mt][nt], ah[mt], bh[nt]);
                mma16816(d[mt][nt], al[mt], bh[nt]);
                mma16816(d[mt][nt], ah[mt], bl[nt]);
            }

        __syncthreads();
        if (ks + 2 < KSTEPS) ISSUE(ks + 2, buf);
    }
#undef ISSUE

    const int grp = lane >> 2, tig = lane & 3;
#pragma unroll
    for (int mt = 0; mt < 4; mt++) {
#pragma unroll
        for (int nt = 0; nt < 4; nt++) {
            int col = bn + wn * 32 + nt * 8 + tig * 2;
            if (col >= LTOT) continue;
#pragma unroll
            for (int half = 0; half < 2; half++) {
                int r = bm + wm * 64 + mt * 16 + grp + half * 8;
                if (r >= M) continue;
                float v0 = d[mt][nt][half * 2 + 0];
                float v1 = d[mt][nt][half * 2 + 1];
                if (r < Msplit) {
                    float bs = bias ? bias[r] : 0.f;
                    float2 o; o.x = v0 + bs; o.y = v1 + bs;
                    *(float2*)(C0 + (long)b * sC0 + (long)r * LTOT + col) = o;
                } else {
                    float2 o; o.x = v0; o.y = v1;
                    *(float2*)(C1 + (long)b * sC1 + (long)(r - Msplit) * LTOT + col) = o;
                }
            }
        }
    }
}

// ---------------------------------------------------------------------------
// In-place softmax over d (9 values) for each (b, head, pixel, i).
// Channel o = (i*9+d)*NHEADS + n; coalesced over pixels.
// grid (LTOT/224, NHEADS, BATCH), block 224.
// ---------------------------------------------------------------------------
__global__ __launch_bounds__(224) void softmax_kernel()
{
    const int l = blockIdx.x * 224 + threadIdx.x;
    const int n = blockIdx.y;
    const int b = blockIdx.z;
    float* abase = g_a + (size_t)b * MA * LTOT + (size_t)n * LTOT + l;

#pragma unroll
    for (int i = 0; i < 9; i++) {
        float* ap = abase + (size_t)(i * 9) * NHEADS * LTOT;
        float lg[9];
        float mx = -1e30f;
#pragma unroll
        for (int dd = 0; dd < 9; dd++) {
            lg[dd] = ap[(size_t)dd * NHEADS * LTOT];
            mx = fmaxf(mx, lg[dd]);
        }
        float s = 0.f;
#pragma unroll
        for (int dd = 0; dd < 9; dd++) { lg[dd] = __expf(lg[dd] - mx); s += lg[dd]; }
        float inv = 1.f / s;
#pragma unroll
        for (int dd = 0; dd < 9; dd++)
            ap[(size_t)dd * NHEADS * LTOT] = lg[dd] * inv;
    }
}

// ---------------------------------------------------------------------------
// Fused attention + fold (gather). Weights read DIRECTLY from softmaxed g_a
// (no smem staging — only the v tile lives in smem; 37.5 KB -> high occ).
// Block 224 threads = (w 0..55) x (channel quarter 0..3). Grid (HH, NHEADS, B).
// ---------------------------------------------------------------------------
__global__ __launch_bounds__(224) void attn_fold_kernel()
{
    __shared__ float vsm[32 * 5 * 60];      // [32 ch][5 rows][60 cols]

    const int h = blockIdx.x;
    const int n = blockIdx.y;
    const int b = blockIdx.z;
    const int tid = threadIdx.x;

    // phase 1: v tile (zero-padded halo)
    const float* vbase = g_v + ((size_t)b * CDIM + (size_t)n * HDIM) * LTOT;
    for (int idx = tid; idx < 32 * 5 * 60; idx += 224) {
        int c   = idx / 300;
        int rem = idx - c * 300;
        int r   = rem / 60;
        int col = rem - r * 60;
        int gr = h - 2 + r;
        int gc = col - 2;
        float val = 0.f;
        if (gr >= 0 && gr < HH && gc >= 0 && gc < WWID)
            val = vbase[(size_t)c * LTOT + gr * WWID + gc];
        vsm[idx] = val;
    }
    __syncthreads();

    // phase 2: combine 81 softmax weights (direct gmem) into 25 per-delta sums
    const int w  = tid % 56;
    const int cq = tid / 56;

    const float* abase = g_a + (size_t)b * MA * LTOT + (size_t)n * LTOT;

    float wsum[25];
#pragma unroll
    for (int q = 0; q < 25; q++) wsum[q] = 0.f;

#pragma unroll
    for (int ii = 0; ii < 3; ii++) {
        int hp = h + 1 - ii;
        if (hp < 0 || hp >= HH) continue;
#pragma unroll
        for (int jj = 0; jj < 3; jj++) {
            int wp = w + 1 - jj;
            if (wp < 0 || wp >= WWID) continue;
            // source pixel (hp, wp), window index i = ii*3+jj
            const float* wp9 = abase
                + (size_t)((ii * 3 + jj) * 9) * NHEADS * LTOT
                + (size_t)hp * WWID + wp;
#pragma unroll
            for (int di = 0; di < 3; di++)
#pragma unroll
                for (int dj = 0; dj < 3; dj++)
                    wsum[(di - ii + 2) * 5 + (dj - jj + 2)] +=
                        __ldg(wp9 + (size_t)(di * 3 + dj) * NHEADS * LTOT);
        }
    }

    // phase 3: weighted gather over the 5x5 delta window, 8 channels each
    float acc[8];
#pragma unroll
    for (int j = 0; j < 8; j++) acc[j] = 0.f;

#pragma unroll
    for (int dr = 0; dr < 5; dr++)
#pragma unroll
        for (int dc = 0; dc < 5; dc++) {
            float wv = wsum[dr * 5 + dc];
            int off = dr * 60 + (w + dc);
#pragma unroll
            for (int j = 0; j < 8; j++)
                acc[j] += wv * vsm[(cq * 8 + j) * 300 + off];
        }

    size_t obase = ((size_t)b * CDIM + (size_t)n * HDIM + cq * 8) * LTOT
                 + (size_t)h * WWID + w;
#pragma unroll
    for (int j = 0; j < 8; j++) {
        float a = acc[j];
        __nv_bfloat16 hh = __float2bfloat16(a);
        __nv_bfloat16 ll = __float2bfloat16(a - __bfloat162float(hh));
        g_fhi[obase + (size_t)j * LTOT] = hh;
        g_flo[obase + (size_t)j * LTOT] = ll;
    }
}

// ---------------------------------------------------------------------------
// Launch. Order keeps launch #6 (ncu -s 5 -c 1) on attn_fold_kernel.
// ---------------------------------------------------------------------------
extern "C" void kernel_launch(void* const* d_in, const int* in_sizes, int n_in,
                              void* d_out, int out_size)
{
    const float* x      = (const float*)d_in[0];
    const float* v_w    = (const float*)d_in[1];
    const float* v_b    = (const float*)d_in[2];
    const float* attn_w = (const float*)d_in[3];
    const float* proj_w = (const float*)d_in[4];
    float* out = (float*)d_out;

    float *gv, *ga;
    __nv_bfloat16 *gxh, *gxl, *gwh, *gwl, *gph, *gpl, *gfh, *gfl;
    cudaGetSymbolAddress((void**)&gv,  g_v);
    cudaGetSymbolAddress((void**)&ga,  g_a);
    cudaGetSymbolAddress((void**)&gxh, g_xhi);
    cudaGetSymbolAddress((void**)&gxl, g_xlo);
    cudaGetSymbolAddress((void**)&gwh, g_whi);
    cudaGetSymbolAddress((void**)&gwl, g_wlo);
    cudaGetSymbolAddress((void**)&gph, g_pwhi);
    cudaGetSymbolAddress((void**)&gpl, g_pwlo);
    cudaGetSymbolAddress((void**)&gfh, g_fhi);
    cudaGetSymbolAddress((void**)&gfl, g_flo);

    // 1-3. splits for x and [v_w ; attn_w]
    {
        int n4 = (BATCH * CDIM * LTOT) / 4;
        split_f32<<<(n4 + 255) / 256, 256>>>((const float4*)x, (uint2*)gxh, (uint2*)gxl, n4);
        int nw = (CDIM * CDIM) / 4;
        split_f32<<<(nw + 255) / 256, 256>>>((const float4*)v_w, (uint2*)gwh, (uint2*)gwl, nw);
        int na = (MA * CDIM) / 4;
        split_f32<<<(na + 255) / 256, 256>>>((const float4*)attn_w,
                                             (uint2*)(gwh + (size_t)CDIM * CDIM),
                                             (uint2*)(gwl + (size_t)CDIM * CDIM), na);
    }

    // 4. fused [v_w ; attn_w] @ x  ->  g_v (+bias) and g_a
    {
        dim3 grid((LTOT + 127) / 128, (MCAT + 127) / 128, BATCH);   // 25 x 11 x 8
        hgemm128<<<grid, 256>>>(gwh, gwl, gxh, gxl, v_b,
                                gv, (long)CDIM * LTOT,
                                ga, (long)MA * LTOT,
                                MCAT, CDIM);
    }

    // 5. in-place softmax of attn logits
    {
        dim3 grid(LTOT / 224, NHEADS, BATCH);   // 14 x 12 x 8
        softmax_kernel<<<grid, 224>>>();
    }

    // 6. fused attention + fold  (writes bf16 hi/lo fold)  [profiled launch]
    {
        dim3 grid(HH, NHEADS, BATCH);
        attn_fold_kernel<<<grid, 224>>>();
    }

    // 7. split proj weights
    {
        int nw = (CDIM * CDIM) / 4;
        split_f32<<<(nw + 255) / 256, 256>>>((const float4*)proj_w, (uint2*)gph, (uint2*)gpl, nw);
    }

    // 8. out = proj_w @ fold
    {
        dim3 grid((LTOT + 127) / 128, (CDIM + 127) / 128, BATCH);   // 25 x 3 x 8
        hgemm128<<<grid, 256>>>(gph, gpl, gfh, gfl, nullptr,
                                out, (long)CDIM * LTOT,
                                out, (long)CDIM * LTOT,
                                CDIM, CDIM);
    }
}